// round 1
// baseline (speedup 1.0000x reference)
#include <cuda_runtime.h>

// Problem constants (fixed by the dataset).
static constexpr int BSZ = 16384;  // batch
static constexpr int HD  = 1024;   // hidden
static constexpr int DD  = 512;    // input/output feature dim

// Tiling.
static constexpr int BM = 64;   // rows (batch) per block
static constexpr int BN = 64;   // output cols per block
static constexpr int BK = 16;   // k-chunk
static constexpr int TM = 4;    // rows per thread
static constexpr int TN = 4;    // cols per thread
static constexpr int NTHREADS = (BM / TM) * (BN / TN);  // 256

// Scratch for intermediate hidden states (allocation-free contract: __device__ globals).
__device__ float g_h0[(size_t)BSZ * HD];
__device__ float g_h1[(size_t)BSZ * HD];

typedef unsigned long long u64;

// ---- packed f32x2 helpers (Blackwell packed-pair FMA: 2x fp32 throughput) ----
__device__ __forceinline__ u64 pack_dup(float a) {
    u64 r;
    unsigned ai = __float_as_uint(a);
    asm("mov.b64 %0, {%1, %1};" : "=l"(r) : "r"(ai));
    return r;
}
__device__ __forceinline__ void fma2(u64 &acc, u64 a, u64 b) {
    asm("fma.rn.f32x2 %0, %1, %2, %0;" : "+l"(acc) : "l"(a), "l"(b));
}
__device__ __forceinline__ float2 unpack2(u64 v) {
    unsigned lo, hi;
    asm("mov.b64 {%0, %1}, %2;" : "=r"(lo), "=r"(hi) : "l"(v));
    return make_float2(__uint_as_float(lo), __uint_as_float(hi));
}
__device__ __forceinline__ float sigm(float x) { return 1.0f / (1.0f + __expf(-x)); }

// One fused GEMM kernel.
//   LSTM=true : computes i/g/o gates (3 accumulators) of  A @ W_gateᵀ,
//               applies   h = sigmoid(i) ⊙ tanh  ... LSTM cell with zero state:
//               c = sigmoid(i)*tanh(g);  h = sigmoid(o)*tanh(c).
//               W rows: [0,H)=i, [H,2H)=f (DEAD, skipped), [2H,3H)=g, [3H,4H)=o.
//   LSTM=false: plain  A @ Wᵀ + b  (decoder).
// K  = reduction dim, NC = output row stride (= #output cols).
template<int K, int NC, bool LSTM>
__global__ __launch_bounds__(NTHREADS)
void gemm_kernel(const float* __restrict__ A, const float* __restrict__ W,
                 const float* __restrict__ b0, const float* __restrict__ b1,
                 float* __restrict__ out)
{
    constexpr int NG = LSTM ? 3 : 1;

    // Transposed tiles: As[k][m], Ws[g][k][n] -> contiguous float4 LDS reads.
    __shared__ __align__(16) float As[BK][BM];
    __shared__ __align__(16) float Ws[NG][BK][BN];

    const int tid  = threadIdx.x;
    const int tx   = tid & 15;     // col group 0..15
    const int ty   = tid >> 4;     // row group 0..15
    const int row0 = blockIdx.y * BM;
    const int col0 = blockIdx.x * BN;

    // Global-load mapping: one float4 per thread per tile.
    const int lrow = tid >> 2;           // 0..63
    const int lk   = (tid & 3) * 4;      // 0,4,8,12

    const float* aptr = A + (size_t)(row0 + lrow) * K + lk;
    const float* wptr[NG];
    wptr[0] = W + (size_t)(0 * HD + col0 + lrow) * K + lk;          // i (or decoder row)
    if constexpr (LSTM) {
        wptr[1] = W + (size_t)(2 * HD + col0 + lrow) * K + lk;      // g
        wptr[2] = W + (size_t)(3 * HD + col0 + lrow) * K + lk;      // o
    }

    u64 acc[NG][TM][TN / 2];
    #pragma unroll
    for (int g = 0; g < NG; g++)
        #pragma unroll
        for (int r = 0; r < TM; r++)
            #pragma unroll
            for (int p = 0; p < TN / 2; p++)
                acc[g][r][p] = 0ull;

    for (int k0 = 0; k0 < K; k0 += BK) {
        // Stage tiles (transposed stores).
        float4 av = *(const float4*)(aptr + k0);
        float4 wv[NG];
        #pragma unroll
        for (int g = 0; g < NG; g++) wv[g] = *(const float4*)(wptr[g] + k0);

        As[lk + 0][lrow] = av.x;
        As[lk + 1][lrow] = av.y;
        As[lk + 2][lrow] = av.z;
        As[lk + 3][lrow] = av.w;
        #pragma unroll
        for (int g = 0; g < NG; g++) {
            Ws[g][lk + 0][lrow] = wv[g].x;
            Ws[g][lk + 1][lrow] = wv[g].y;
            Ws[g][lk + 2][lrow] = wv[g].z;
            Ws[g][lk + 3][lrow] = wv[g].w;
        }
        __syncthreads();

        #pragma unroll
        for (int kk = 0; kk < BK; kk++) {
            float4 a4 = *(const float4*)&As[kk][ty * TM];
            u64 ad[TM];
            ad[0] = pack_dup(a4.x);
            ad[1] = pack_dup(a4.y);
            ad[2] = pack_dup(a4.z);
            ad[3] = pack_dup(a4.w);
            #pragma unroll
            for (int g = 0; g < NG; g++) {
                ulonglong2 w2 = *(const ulonglong2*)&Ws[g][kk][tx * TN];
                #pragma unroll
                for (int r = 0; r < TM; r++) {
                    fma2(acc[g][r][0], ad[r], w2.x);
                    fma2(acc[g][r][1], ad[r], w2.y);
                }
            }
        }
        __syncthreads();
    }

    // ---- Epilogue ----
    const int cbase = col0 + tx * TN;
    if constexpr (LSTM) {
        float bi[TN], bg[TN], bo[TN];
        #pragma unroll
        for (int j = 0; j < TN; j++) {
            int n = cbase + j;
            bi[j] = b0[n]          + b1[n];
            bg[j] = b0[2 * HD + n] + b1[2 * HD + n];
            bo[j] = b0[3 * HD + n] + b1[3 * HD + n];
        }
        #pragma unroll
        for (int r = 0; r < TM; r++) {
            int m = row0 + ty * TM + r;
            float h[TN];
            #pragma unroll
            for (int p = 0; p < TN / 2; p++) {
                float2 vi = unpack2(acc[0][r][p]);
                float2 vg = unpack2(acc[1][r][p]);
                float2 vo = unpack2(acc[2][r][p]);
                {
                    float iv = sigm(vi.x + bi[2 * p]);
                    float gv = tanhf(vg.x + bg[2 * p]);
                    float ov = sigm(vo.x + bo[2 * p]);
                    h[2 * p] = ov * tanhf(iv * gv);
                }
                {
                    float iv = sigm(vi.y + bi[2 * p + 1]);
                    float gv = tanhf(vg.y + bg[2 * p + 1]);
                    float ov = sigm(vo.y + bo[2 * p + 1]);
                    h[2 * p + 1] = ov * tanhf(iv * gv);
                }
            }
            *(float4*)&out[(size_t)m * NC + cbase] = make_float4(h[0], h[1], h[2], h[3]);
        }
    } else {
        float bb[TN];
        #pragma unroll
        for (int j = 0; j < TN; j++) bb[j] = b0[cbase + j];
        #pragma unroll
        for (int r = 0; r < TM; r++) {
            int m = row0 + ty * TM + r;
            float2 v0 = unpack2(acc[0][r][0]);
            float2 v1 = unpack2(acc[0][r][1]);
            *(float4*)&out[(size_t)m * NC + cbase] =
                make_float4(v0.x + bb[0], v0.y + bb[1], v1.x + bb[2], v1.y + bb[3]);
        }
    }
}

extern "C" void kernel_launch(void* const* d_in, const int* in_sizes, int n_in,
                              void* d_out, int out_size) {
    // metadata order: x, W_ih0, W_hh0, b_ih0, b_hh0, W_ih1, W_hh1, b_ih1, b_hh1, W_dec, b_dec
    const float* x     = (const float*)d_in[0];
    const float* W_ih0 = (const float*)d_in[1];
    // d_in[2] = W_hh0 : dead (h0 = 0)
    const float* b_ih0 = (const float*)d_in[3];
    const float* b_hh0 = (const float*)d_in[4];
    const float* W_ih1 = (const float*)d_in[5];
    // d_in[6] = W_hh1 : dead
    const float* b_ih1 = (const float*)d_in[7];
    const float* b_hh1 = (const float*)d_in[8];
    const float* W_dec = (const float*)d_in[9];
    const float* b_dec = (const float*)d_in[10];
    float* out = (float*)d_out;

    float *h0 = nullptr, *h1 = nullptr;
    cudaGetSymbolAddress((void**)&h0, g_h0);
    cudaGetSymbolAddress((void**)&h1, g_h1);

    dim3 blk(NTHREADS);
    dim3 g_lstm(HD / BN, BSZ / BM);   // 16 x 256
    dim3 g_dec(DD / BN, BSZ / BM);    // 8 x 256

    gemm_kernel<DD, HD, true ><<<g_lstm, blk>>>(x,  W_ih0, b_ih0, b_hh0, h0);
    gemm_kernel<HD, HD, true ><<<g_lstm, blk>>>(h0, W_ih1, b_ih1, b_hh1, h1);
    gemm_kernel<HD, DD, false><<<g_dec,  blk>>>(h1, W_dec, b_dec, nullptr, out);
}